// round 15
// baseline (speedup 1.0000x reference)
#include <cuda_runtime.h>
#include <cuda_bf16.h>
#include <cstdint>

#define BB 8
#define SS 4096
#define HH 1024
#define KK 2048      // K = 0.5 * S
#define NBIN 4096    // uniform bins over score in (0,1)
#define MAXC 1024    // candidate buffer cap (E is ~1-6 in practice)

__device__ float g_scores[BB * SS];      // sigmoid(logit)
__device__ int   g_hist[BB * NBIN];      // uniform bins; re-zeroed by topk

__device__ __forceinline__ uint32_t orderable(float f) {
    uint32_t u = __float_as_uint(f);
    return u ^ ((u >> 31) ? 0xFFFFFFFFu : 0x80000000u);
}

// Monotone uniform bin for score in (0,1). floor(s*4096), clamped.
__device__ __forceinline__ int score_bin(float s) {
    int b = (int)(s * 4096.0f);
    return min(max(b, 0), NBIN - 1);
}

// ---------------------------------------------------------------------------
// Pass 1: router GEMV, ONE token per warp (R3 shape: fastest measured).
// Lane 0 applies sigmoid, stores the score, and bins the uniform histogram
// via one global red atomic (hidden under the DRAM-bound mainloop).
// ---------------------------------------------------------------------------
__global__ __launch_bounds__(256) void router_logits_kernel(
    const float* __restrict__ x, const float* __restrict__ w,
    float* __restrict__ scores, int* __restrict__ hist_g)
{
    int gw   = (blockIdx.x * blockDim.x + threadIdx.x) >> 5;  // token
    int lane = threadIdx.x & 31;
    if (gw >= BB * SS) return;

    const float4* xp = reinterpret_cast<const float4*>(x + (size_t)gw * HH);
    const float4* wp = reinterpret_cast<const float4*>(w);

    float acc = 0.0f;
#pragma unroll
    for (int i = 0; i < 8; i++) {                 // 8 * 32 * 4 = 1024 = H
        int idx = lane + i * 32;
        float4 a = __ldcs(&xp[idx]);              // streaming: read-once data
        float4 b = __ldg(&wp[idx]);
        acc = fmaf(a.x, b.x, acc);
        acc = fmaf(a.y, b.y, acc);
        acc = fmaf(a.z, b.z, acc);
        acc = fmaf(a.w, b.w, acc);
    }
#pragma unroll
    for (int o = 16; o; o >>= 1)
        acc += __shfl_xor_sync(0xFFFFFFFFu, acc, o);

    if (lane == 0) {
        float s = 1.0f / (1.0f + expf(-acc));
        scores[gw] = s;
        int* hrow = hist_g + (gw >> 12) * NBIN;   // row = gw / SS
        atomicAdd(&hrow[score_bin(s)], 1);
    }
}

// ---------------------------------------------------------------------------
// Pass 2: per-row exact top-K + emit. One block (1024 thr) per row.
// Descending block-scan over 4096 uniform bins (int4 loads, ascending
// layout; "count above" = SS - inclusive_ascending) -> bin P + quota T.
// Candidates sharing bin P (tiny E) get an exact rank count on
// (key desc, idx asc) composites -> resolves ties identically to lax.top_k.
// ---------------------------------------------------------------------------
__global__ __launch_bounds__(1024) void topk_select_kernel(
    const float* __restrict__ scores, int* __restrict__ hist_g,
    float* __restrict__ out, int out_size)
{
    __shared__ int      s_wsum[32];
    __shared__ int      s_wexcl[32];
    __shared__ int      s_P;          // selected bin
    __shared__ int      s_T;          // quota within the bin
    __shared__ int      s_cnt;        // candidate count
    __shared__ uint32_t s_ckey[MAXC];
    __shared__ int      s_cidx[MAXC];
    __shared__ uint32_t s_cut_key;
    __shared__ int      s_cut_idx;

    const int b    = blockIdx.x;
    const int tid  = threadIdx.x;
    const int lane = tid & 31;
    const int wid  = tid >> 5;
    const float* rowp = scores + b * SS;
    int* hrow = hist_g + b * NBIN;

    // Load this thread's 4 consecutive scores; keys in registers.
    float4 lv = *reinterpret_cast<const float4*>(rowp + tid * 4);
    float    v[4] = {lv.x, lv.y, lv.z, lv.w};
    uint32_t k[4];
#pragma unroll
    for (int i = 0; i < 4; i++)
        k[i] = orderable(v[i]);

    if (tid == 0) s_cnt = 0;

    // ---- Block scan over 4096 bins, thread t owns bins [4t..4t+3] ----
    int4 hv = *reinterpret_cast<const int4*>(hrow + tid * 4);   // aligned int4
    int h[4] = {hv.x, hv.y, hv.z, hv.w};
    const int part = h[0] + h[1] + h[2] + h[3];
    // Re-zero consumed bins for the next graph replay.
    *reinterpret_cast<int4*>(hrow + tid * 4) = make_int4(0, 0, 0, 0);

    // Ascending inclusive scan of chunk sums across the block.
    int inc = part;
#pragma unroll
    for (int o = 1; o < 32; o <<= 1) {
        int t = __shfl_up_sync(0xFFFFFFFFu, inc, o);
        if (lane >= o) inc += t;
    }
    if (lane == 31) s_wsum[wid] = inc;
    __syncthreads();
    if (wid == 0) {
        int wv = s_wsum[lane];
        int winc = wv;
#pragma unroll
        for (int o = 1; o < 32; o <<= 1) {
            int t = __shfl_up_sync(0xFFFFFFFFu, winc, o);
            if (lane >= o) winc += t;
        }
        s_wexcl[lane] = winc - wv;
    }
    __syncthreads();

    {
        // keys in bins strictly ABOVE this thread's chunk
        const int incl_asc = s_wexcl[wid] + inc;     // through bin 4t+3
        const int above = SS - incl_asc;             // hist sums to SS exactly
        if (above < KK && above + part >= KK) {      // unique crossing thread
            int acc = above;
#pragma unroll
            for (int j = 3; j >= 0; j--) {           // descending within chunk
                if (acc + h[j] >= KK) {
                    s_P = tid * 4 + j;
                    s_T = KK - acc;
                    break;
                }
                acc += h[j];
            }
        }
    }
    __syncthreads();

    // ---- Collect candidates in the crossing bin (uniform -> E tiny) ----
    const int P = s_P;
#pragma unroll
    for (int i = 0; i < 4; i++) {
        if (score_bin(v[i]) == P) {
            int pos = atomicAdd(&s_cnt, 1);
            if (pos < MAXC) {
                s_ckey[pos] = k[i];
                s_cidx[pos] = tid * 4 + i;
            }
        }
    }
    __syncthreads();

    // ---- Exact cutoff: candidate with rank T-1 in (key desc, idx asc) ----
    const int E = min(s_cnt, MAXC);
    const int T = s_T;
    for (int c = tid; c < E; c += 1024) {
        uint32_t ck = s_ckey[c];
        int      ci = s_cidx[c];
        int better = 0;
        for (int e = 0; e < E; e++) {
            uint32_t ek = s_ckey[e];
            better += (ek > ck) || (ek == ck && s_cidx[e] < ci);
        }
        if (better == T - 1) {
            s_cut_key = ck;
            s_cut_idx = ci;
        }
    }
    __syncthreads();

    const uint32_t cut_key = s_cut_key;
    const int      cut_idx = s_cut_idx;

    // ---- Emit: accept iff (key,idx) >= cutoff in (key desc, idx asc) ----
    const int  base = b * SS;
    const bool has_mask_half = (out_size >= 2 * BB * SS);
    float wv4[4], mv4[4];
#pragma unroll
    for (int i = 0; i < 4; i++) {
        int s = tid * 4 + i;
        bool m = (k[i] > cut_key) || (k[i] == cut_key && s <= cut_idx);
        wv4[i] = m ? v[i] : 0.0f;
        mv4[i] = m ? 1.0f : 0.0f;
    }
    *reinterpret_cast<float4*>(out + base + tid * 4) =
        make_float4(wv4[0], wv4[1], wv4[2], wv4[3]);
    if (has_mask_half)
        *reinterpret_cast<float4*>(out + BB * SS + base + tid * 4) =
            make_float4(mv4[0], mv4[1], mv4[2], mv4[3]);
}

extern "C" void kernel_launch(void* const* d_in, const int* in_sizes, int n_in,
                              void* d_out, int out_size)
{
    const float* hidden = (const float*)d_in[0];
    const float* w      = (const float*)d_in[1];
    float* out = (float*)d_out;

    float* scores = nullptr;
    int*   hist   = nullptr;
    cudaGetSymbolAddress((void**)&scores, g_scores);
    cudaGetSymbolAddress((void**)&hist,   g_hist);

    const int tokens = BB * SS;                     // 1 token per warp
    router_logits_kernel<<<tokens / 8, 256>>>(hidden, w, scores, hist);
    topk_select_kernel<<<BB, 1024>>>(scores, hist, out, out_size);
}